// round 13
// baseline (speedup 1.0000x reference)
#include <cuda_runtime.h>
#include <math.h>

#define NN 50000
#define EE 500000

// node-space tables
__device__ __align__(16) float4 g_q[NN * 32];
__device__ __align__(16) float4 g_k[NN * 32];
__device__ __align__(16) float4 g_v[NN * 32];
__device__ __align__(16) float4 g_z[NN * 96];      // [n][2][192] flat [n][384]
// per-dst aggregates (atomically accumulated; memset each launch)
__device__ __align__(16) float4 g_aggT[NN * 32];   // [n][2][64]   sum w*enc
__device__ __align__(16) float4 g_aggM[NN * 64];   // [n][2][128]  sum w*msg
__device__ __align__(16) float4 g_aggV[NN * 32];   // [n][2][64]   sum w*v[src]
__device__ __align__(8)  float2 g_asum[NN];        // [n][2]       sum w
__device__ int g_is64;
// combined weights: cols [q(0) k(128) v(256) skip(384)]
__device__ __align__(16) float g_Wall[128 * 512];
__device__ __align__(16) float g_ball[512];
// transposed We per head: g_WeT[h][c][d] = We[d*128 + h*64 + c]
__device__ __align__(16) float g_WeT[2 * 64 * 192];

static __device__ __forceinline__ float dot4(float4 a, float4 b) {
    return a.x * b.x + a.y * b.y + a.z * b.z + a.w * b.w;
}
static __device__ __forceinline__ void red4(float4* p, float x, float y, float z, float w) {
    asm volatile("red.global.add.v4.f32 [%0], {%1,%2,%3,%4};"
                 :: "l"(p), "f"(x), "f"(y), "f"(z), "f"(w) : "memory");
}
static __device__ __forceinline__ void red2(float2* p, float x, float y) {
    asm volatile("red.global.add.v2.f32 [%0], {%1,%2};"
                 :: "l"(p), "f"(x), "f"(y) : "memory");
}

// ---------------------------------------------------------------------------
__global__ void k_detect(const int* __restrict__ ei32) {
    int odd_or = 0;
    #pragma unroll
    for (int i = 1; i < 64; i += 2) odd_or |= ei32[i];
    g_is64 = (odd_or == 0) ? 1 : 0;
}

// ---------------------------------------------------------------------------
// Kp: Wall [128][512] copy + bias [512] + transposed We table.
// ---------------------------------------------------------------------------
__global__ void k_prep(const float* __restrict__ Wq, const float* __restrict__ bq,
                       const float* __restrict__ Wk, const float* __restrict__ bk,
                       const float* __restrict__ Wv, const float* __restrict__ bv,
                       const float* __restrict__ Ws, const float* __restrict__ bs,
                       const float* __restrict__ We)
{
    int u = blockIdx.x * 256 + threadIdx.x;
    if (u < 128 * 512) {
        int j = u >> 9, c = u & 511;
        const float* src = (c < 128) ? Wq : (c < 256) ? Wk : (c < 384) ? Wv : Ws;
        g_Wall[u] = src[j * 128 + (c & 127)];
    } else if (u < 128 * 512 + 2 * 64 * 192) {
        int v = u - 128 * 512;
        int h = v / 12288, r = v % 12288;
        int c = r / 192, d = r % 192;
        g_WeT[v] = We[d * 128 + h * 64 + c];
    } else if (u < 128 * 512 + 2 * 64 * 192 + 512) {
        int c = u - (128 * 512 + 2 * 64 * 192);
        const float* src = (c < 128) ? bq : (c < 256) ? bk : (c < 384) ? bv : bs;
        g_ball[c] = src[c & 127];
    }
}

// ---------------------------------------------------------------------------
// K1: node GEMM [50000,128] @ [128,512] (q,k,v,skip). Tile 128x128, 8x8/thr.
// ---------------------------------------------------------------------------
__global__ void __launch_bounds__(256, 2)
k_gemm(const float* __restrict__ x, float* __restrict__ out)
{
    __shared__ float xs[32][132];   // [k][m] transposed x panel
    __shared__ float ws[32][128];   // [k][n]
    const int t = threadIdx.x;
    const int y = blockIdx.y;
    const int col0 = y * 128;

    float* dptr;
    if      (y == 0) dptr = (float*)g_q;
    else if (y == 1) dptr = (float*)g_k;
    else if (y == 2) dptr = (float*)g_v;
    else             dptr = out;

    const int m0 = blockIdx.x * 128;
    const float4* x4 = (const float4*)x;
    const int tn = t & 15, tm = t >> 4;

    float4 acc[8][2];
    #pragma unroll
    for (int r = 0; r < 8; r++) { acc[r][0] = make_float4(0.f,0.f,0.f,0.f); acc[r][1] = acc[r][0]; }

#define FMA4(A, S, Bv) { A.x += (S)*(Bv).x; A.y += (S)*(Bv).y; A.z += (S)*(Bv).z; A.w += (S)*(Bv).w; }
    for (int k0 = 0; k0 < 128; k0 += 32) {
        #pragma unroll
        for (int i = t; i < 1024; i += 256) {
            int m = i >> 3, c4 = i & 7;
            int node = m0 + m;
            float4 v = (node < NN) ? x4[(size_t)node * 32 + (k0 >> 2) + c4]
                                   : make_float4(0.f, 0.f, 0.f, 0.f);
            int kk = c4 * 4;
            xs[kk + 0][m] = v.x; xs[kk + 1][m] = v.y;
            xs[kk + 2][m] = v.z; xs[kk + 3][m] = v.w;
        }
        #pragma unroll
        for (int i = t; i < 1024; i += 256) {
            int kk = i >> 5, c4 = i & 31;
            *(float4*)&ws[kk][c4 * 4] = *(const float4*)&g_Wall[(size_t)(k0 + kk) * 512 + col0 + c4 * 4];
        }
        __syncthreads();

        #pragma unroll
        for (int kk = 0; kk < 32; kk++) {
            float4 a0 = *(const float4*)&xs[kk][tm * 8];
            float4 a1 = *(const float4*)&xs[kk][tm * 8 + 4];
            float4 b0 = *(const float4*)&ws[kk][tn * 8];
            float4 b1 = *(const float4*)&ws[kk][tn * 8 + 4];
            FMA4(acc[0][0], a0.x, b0); FMA4(acc[0][1], a0.x, b1);
            FMA4(acc[1][0], a0.y, b0); FMA4(acc[1][1], a0.y, b1);
            FMA4(acc[2][0], a0.z, b0); FMA4(acc[2][1], a0.z, b1);
            FMA4(acc[3][0], a0.w, b0); FMA4(acc[3][1], a0.w, b1);
            FMA4(acc[4][0], a1.x, b0); FMA4(acc[4][1], a1.x, b1);
            FMA4(acc[5][0], a1.y, b0); FMA4(acc[5][1], a1.y, b1);
            FMA4(acc[6][0], a1.z, b0); FMA4(acc[6][1], a1.z, b1);
            FMA4(acc[7][0], a1.w, b0); FMA4(acc[7][1], a1.w, b1);
        }
        __syncthreads();
    }

    float4 bb0 = *(const float4*)&g_ball[col0 + tn * 8];
    float4 bb1 = *(const float4*)&g_ball[col0 + tn * 8 + 4];
    #pragma unroll
    for (int r = 0; r < 8; r++) {
        int node = m0 + tm * 8 + r;
        if (node >= NN) break;
        float4 o0 = acc[r][0]; o0.x += bb0.x; o0.y += bb0.y; o0.z += bb0.z; o0.w += bb0.w;
        float4 o1 = acc[r][1]; o1.x += bb1.x; o1.y += bb1.y; o1.z += bb1.z; o1.w += bb1.w;
        float* p = dptr + (size_t)node * 128 + tn * 8;
        *(float4*)p = o0;
        *(float4*)(p + 4) = o1;
    }
}

// ---------------------------------------------------------------------------
// K1b: z GEMM from q: z[n,h,d] = sum_c q[n,h,c] * WeT[h][c][d], k=64.
// ---------------------------------------------------------------------------
__global__ void __launch_bounds__(256, 2)
k_gemmz()
{
    __shared__ float xs[32][132];   // [k][m] transposed q_h panel
    __shared__ float ws[32][68];    // [k][n]
    const int t = threadIdx.x;
    const int head = blockIdx.y / 3;
    const int nt = blockIdx.y % 3;
    const int col0 = nt * 64;
    const int m0 = blockIdx.x * 128;

    const float4* q4 = (const float4*)g_q;
    const float4* wt4 = (const float4*)(g_WeT + head * 12288);
    const int tn = t & 15, tm = t >> 4;

    float4 acc[8];
    #pragma unroll
    for (int r = 0; r < 8; r++) acc[r] = make_float4(0.f, 0.f, 0.f, 0.f);

    for (int k0 = 0; k0 < 64; k0 += 32) {
        #pragma unroll
        for (int i = t; i < 1024; i += 256) {
            int m = i >> 3, c4 = i & 7;
            int node = m0 + m;
            float4 v = (node < NN) ? q4[(size_t)node * 32 + head * 16 + (k0 >> 2) + c4]
                                   : make_float4(0.f, 0.f, 0.f, 0.f);
            int kk = c4 * 4;
            xs[kk + 0][m] = v.x; xs[kk + 1][m] = v.y;
            xs[kk + 2][m] = v.z; xs[kk + 3][m] = v.w;
        }
        #pragma unroll
        for (int i = t; i < 512; i += 256) {
            int kk = i >> 4, c4 = i & 15;
            *(float4*)&ws[kk][c4 * 4] = wt4[(size_t)(k0 + kk) * 48 + nt * 16 + c4];
        }
        __syncthreads();

        #pragma unroll
        for (int kk = 0; kk < 32; kk++) {
            float4 a0 = *(const float4*)&xs[kk][tm * 8];
            float4 a1 = *(const float4*)&xs[kk][tm * 8 + 4];
            float4 b0 = *(const float4*)&ws[kk][tn * 4];
            FMA4(acc[0], a0.x, b0);
            FMA4(acc[1], a0.y, b0);
            FMA4(acc[2], a0.z, b0);
            FMA4(acc[3], a0.w, b0);
            FMA4(acc[4], a1.x, b0);
            FMA4(acc[5], a1.y, b0);
            FMA4(acc[6], a1.z, b0);
            FMA4(acc[7], a1.w, b0);
        }
        __syncthreads();
    }
#undef FMA4

    float* zf = (float*)g_z;
    #pragma unroll
    for (int r = 0; r < 8; r++) {
        int node = m0 + tm * 8 + r;
        if (node >= NN) break;
        *(float4*)&zf[(size_t)node * 384 + head * 192 + col0 + tn * 4] = acc[r];
    }
}

// ---------------------------------------------------------------------------
// K2: warp per edge, NATURAL order (coalesced msg/tt streams, 500K
// independent warps -> latency fully hidden). Per-lane enc quartet,
// folded qk reduction, red.v4 atomics into per-dst aggregates.
// (R2 structure, ncu-measured 375us @ DRAM 85%)
// ---------------------------------------------------------------------------
__global__ void __launch_bounds__(256)
k_edge(const void* __restrict__ ei,
       const float* __restrict__ tt,
       const float* __restrict__ lu,
       const float4* __restrict__ msg4,
       const float* __restrict__ tw,
       const float* __restrict__ tb)
{
    const int w = threadIdx.x >> 5, lane = threadIdx.x & 31;
    const size_t e = (size_t)blockIdx.x * 8 + w;
    if (e >= EE) return;

    int src, dst;
    if (g_is64) {
        src = (int)((const long long*)ei)[e];
        dst = (int)((const long long*)ei)[EE + e];
    } else {
        src = ((const int*)ei)[e];
        dst = ((const int*)ei)[EE + e];
    }
    const float rel = tt[e] - lu[src];

    const int lq = lane & 15;
    const float4 tw4 = ((const float4*)tw)[lq];
    const float4 tb4 = ((const float4*)tb)[lq];
    float4 ev;
    ev.x = __cosf(rel * tw4.x + tb4.x);
    ev.y = __cosf(rel * tw4.y + tb4.y);
    ev.z = __cosf(rel * tw4.z + tb4.z);
    ev.w = __cosf(rel * tw4.w + tb4.w);

    const size_t mb = e * 32;
    float4 q4 = g_q[(size_t)dst * 32 + lane];
    float4 k4 = g_k[(size_t)src * 32 + lane];
    float4 v4 = g_v[(size_t)src * 32 + lane];
    float4 m4 = msg4[mb + lane];
    float4 xm = msg4[mb + (lane ^ 16)];

    const size_t zb0 = (size_t)dst * 96;
    float4 za = g_z[zb0 + lane];
    float4 zb = g_z[zb0 + 32 + lane];
    float4 zc = g_z[zb0 + 64 + lane];

    float qk = dot4(q4, k4);
    float4 Aa = (lane < 16) ? ev : xm;
    float4 Ab = (lane < 16) ? xm : ev;
    float pb = dot4(zb, Ab) + qk;
    float p0 = dot4(za, Aa) + ((lane < 16) ? pb : 0.f);
    float p1 = dot4(zc, m4) + ((lane < 16) ? 0.f : pb);
    #pragma unroll
    for (int o = 16; o >= 1; o >>= 1) {
        p0 += __shfl_xor_sync(0xffffffffu, p0, o);
        p1 += __shfl_xor_sync(0xffffffffu, p1, o);
    }

    float w0 = __expf(0.125f * p0);
    float w1 = __expf(0.125f * p1);

    float sc = (lane < 16) ? w0 : w1;
    red4(&g_aggT[(size_t)dst * 32 + lane], sc * ev.x, sc * ev.y, sc * ev.z, sc * ev.w);
    red4(&g_aggV[(size_t)dst * 32 + lane], sc * v4.x, sc * v4.y, sc * v4.z, sc * v4.w);
    red4(&g_aggM[(size_t)dst * 64 + lane],      w0 * m4.x, w0 * m4.y, w0 * m4.z, w0 * m4.w);
    red4(&g_aggM[(size_t)dst * 64 + 32 + lane], w1 * m4.x, w1 * m4.y, w1 * m4.z, w1 * m4.w);
    if (lane == 0) red2(&g_asum[dst], w0, w1);
}

// ---------------------------------------------------------------------------
// K3: out[n,h,c] += (aggV[n,h,c] + sum_d aggE[n,h,d]*We[d,h*64+c]) / asum[n,h]
// ---------------------------------------------------------------------------
__global__ void k_final(const float* __restrict__ We, float* __restrict__ out)
{
    extern __shared__ float smf[];
    float* WeS = smf;                // 192 x 132
    float* sA  = smf + 192 * 132;    // 4 x 392
    float* sS  = sA + 4 * 392;       // 8 asums
    const int t = threadIdx.x;       // 128

    const float4* We4 = (const float4*)We;
    for (int i = t; i < 192 * 32; i += 128) {
        int d = i >> 5, c4 = i & 31;
        ((float4*)(WeS + d * 132))[c4] = We4[i];
    }

    const int j = t, h = t >> 6;
    for (int q0 = blockIdx.x * 4; q0 < NN; q0 += gridDim.x * 4) {
        __syncthreads();
        for (int i = t; i < 4 * 96; i += 128) {
            int ni = i / 96, m = i % 96;
            int node = q0 + ni;
            int hh = m / 48, d4 = m % 48;
            float4 val = (d4 < 16) ? g_aggT[(size_t)node * 32 + hh * 16 + d4]
                                   : g_aggM[(size_t)node * 64 + hh * 32 + (d4 - 16)];
            *(float4*)&sA[ni * 392 + hh * 196 + d4 * 4] = val;
        }
        if (t < 8) sS[t] = ((const float*)g_asum)[(size_t)(q0 + (t >> 1)) * 2 + (t & 1)];
        __syncthreads();

        float acc0 = 0.f, acc1 = 0.f, acc2 = 0.f, acc3 = 0.f;
        const float* a0 = sA + 0 * 392 + h * 196;
        const float* a1 = sA + 1 * 392 + h * 196;
        const float* a2 = sA + 2 * 392 + h * 196;
        const float* a3 = sA + 3 * 392 + h * 196;
        #pragma unroll 4
        for (int d = 0; d < 192; d++) {
            float wv = WeS[d * 132 + j];
            acc0 += wv * a0[d];
            acc1 += wv * a1[d];
            acc2 += wv * a2[d];
            acc3 += wv * a3[d];
        }

        const float* gv = (const float*)g_aggV;
        size_t n0 = (size_t)q0;
        out[(n0 + 0) * 128 + j] += (gv[(n0 + 0) * 128 + j] + acc0) * (1.f / (sS[0 + h] + 1e-16f));
        out[(n0 + 1) * 128 + j] += (gv[(n0 + 1) * 128 + j] + acc1) * (1.f / (sS[2 + h] + 1e-16f));
        out[(n0 + 2) * 128 + j] += (gv[(n0 + 2) * 128 + j] + acc2) * (1.f / (sS[4 + h] + 1e-16f));
        out[(n0 + 3) * 128 + j] += (gv[(n0 + 3) * 128 + j] + acc3) * (1.f / (sS[6 + h] + 1e-16f));
    }
}

// ---------------------------------------------------------------------------
extern "C" void kernel_launch(void* const* d_in, const int* in_sizes, int n_in,
                              void* d_out, int out_size)
{
    const float* x  = (const float*)d_in[0];
    const float* lu = (const float*)d_in[1];
    const float* tt = (const float*)d_in[2];
    const float* msg = (const float*)d_in[3];
    const float* tw = (const float*)d_in[4];
    const float* tb = (const float*)d_in[5];
    const float* Wq = (const float*)d_in[6];
    const float* bq = (const float*)d_in[7];
    const float* Wk = (const float*)d_in[8];
    const float* bk = (const float*)d_in[9];
    const float* Wv = (const float*)d_in[10];
    const float* bv = (const float*)d_in[11];
    const float* We = (const float*)d_in[12];
    const float* Ws = (const float*)d_in[13];
    const float* bs = (const float*)d_in[14];
    const void* ei  = d_in[15];
    float* out = (float*)d_out;

    cudaFuncSetAttribute(k_final, cudaFuncAttributeMaxDynamicSharedMemorySize, 107680);

    void *pT, *pM, *pV, *pS;
    cudaGetSymbolAddress(&pT, g_aggT);
    cudaGetSymbolAddress(&pM, g_aggM);
    cudaGetSymbolAddress(&pV, g_aggV);
    cudaGetSymbolAddress(&pS, g_asum);
    cudaMemsetAsync(pT, 0, sizeof(g_aggT));
    cudaMemsetAsync(pM, 0, sizeof(g_aggM));
    cudaMemsetAsync(pV, 0, sizeof(g_aggV));
    cudaMemsetAsync(pS, 0, sizeof(g_asum));

    k_detect<<<1, 1>>>((const int*)ei);                        // kernel 1
    k_prep<<<353, 256>>>(Wq, bq, Wk, bk, Wv, bv, Ws, bs, We);  // kernel 2
    k_detect<<<1, 1>>>((const int*)ei);                        // kernel 3 (pad: puts k_gemm in the ncu 4th-kernel capture slot)
    k_gemm<<<dim3(391, 4, 1), 256>>>(x, out);                  // kernel 4 <- capture
    k_gemmz<<<dim3(391, 6, 1), 256>>>();
    k_edge<<<62500, 256>>>(ei, tt, lu, (const float4*)msg, tw, tb);
    k_final<<<592, 128, 107680>>>(We, out);
}

// round 15
// speedup vs baseline: 1.2333x; 1.2333x over previous
#include <cuda_runtime.h>
#include <math.h>

#define NN 50000
#define EE 500000

// node-space tables
__device__ __align__(16) float4 g_q[NN * 32];
__device__ __align__(16) float4 g_k[NN * 32];
__device__ __align__(16) float4 g_v[NN * 32];
__device__ __align__(16) float4 g_z[NN * 96];      // [n][2][192] flat [n][384]
// per-dst aggregates (written once by k_edge2; no memsets needed)
__device__ __align__(16) float4 g_aggT[NN * 32];   // [n][2][64]   sum w*enc
__device__ __align__(16) float4 g_aggM[NN * 64];   // [n][2][128]  sum w*msg
__device__ __align__(16) float4 g_aggV[NN * 32];   // [n][2][64]   sum w*v[src]
__device__ __align__(8)  float2 g_asum[NN];        // [n][2]       sum w
__device__ int g_is64;
// combined weights: cols [q(0) k(128) v(256) skip(384)]
__device__ __align__(16) float g_Wall[128 * 512];
__device__ __align__(16) float g_ball[512];
// transposed We per head: g_WeT[h][c][d] = We[d*128 + h*64 + c]
__device__ __align__(16) float g_WeT[2 * 64 * 192];
// counting-sort scratch
__device__ int g_cnt[NN];
__device__ int g_offA[NN];
__device__ int g_bsum[128];
__device__ int g_bpre[128];
__device__ int g_off[NN + 1];
__device__ int g_pos[NN];
__device__ int g_eid[EE];

static __device__ __forceinline__ float dot4(float4 a, float4 b) {
    return a.x * b.x + a.y * b.y + a.z * b.z + a.w * b.w;
}

// ---------------------------------------------------------------------------
__global__ void k_detect(const int* __restrict__ ei32) {
    int odd_or = 0;
    #pragma unroll
    for (int i = 1; i < 64; i += 2) odd_or |= ei32[i];
    g_is64 = (odd_or == 0) ? 1 : 0;
}

// ---------------------------------------------------------------------------
// Kp: Wall [128][512] copy + bias [512] + transposed We table.
// ---------------------------------------------------------------------------
__global__ void k_prep(const float* __restrict__ Wq, const float* __restrict__ bq,
                       const float* __restrict__ Wk, const float* __restrict__ bk,
                       const float* __restrict__ Wv, const float* __restrict__ bv,
                       const float* __restrict__ Ws, const float* __restrict__ bs,
                       const float* __restrict__ We)
{
    int u = blockIdx.x * 256 + threadIdx.x;
    if (u < 128 * 512) {
        int j = u >> 9, c = u & 511;
        const float* src = (c < 128) ? Wq : (c < 256) ? Wk : (c < 384) ? Wv : Ws;
        g_Wall[u] = src[j * 128 + (c & 127)];
    } else if (u < 128 * 512 + 2 * 64 * 192) {
        int v = u - 128 * 512;
        int h = v / 12288, r = v % 12288;
        int c = r / 192, d = r % 192;
        g_WeT[v] = We[d * 128 + h * 64 + c];
    } else if (u < 128 * 512 + 2 * 64 * 192 + 512) {
        int c = u - (128 * 512 + 2 * 64 * 192);
        const float* src = (c < 128) ? bq : (c < 256) ? bk : (c < 384) ? bv : bs;
        g_ball[c] = src[c & 127];
    }
}

// ---------------------------------------------------------------------------
// K1: node GEMM [50000,128] @ [128,512] (q,k,v,skip). Tile 128x128, 8x8/thr.
// ---------------------------------------------------------------------------
__global__ void __launch_bounds__(256, 2)
k_gemm(const float* __restrict__ x, float* __restrict__ out)
{
    __shared__ float xs[32][132];   // [k][m] transposed x panel
    __shared__ float ws[32][128];   // [k][n]
    const int t = threadIdx.x;
    const int y = blockIdx.y;
    const int col0 = y * 128;

    float* dptr;
    if      (y == 0) dptr = (float*)g_q;
    else if (y == 1) dptr = (float*)g_k;
    else if (y == 2) dptr = (float*)g_v;
    else             dptr = out;

    const int m0 = blockIdx.x * 128;
    const float4* x4 = (const float4*)x;
    const int tn = t & 15, tm = t >> 4;

    float4 acc[8][2];
    #pragma unroll
    for (int r = 0; r < 8; r++) { acc[r][0] = make_float4(0.f,0.f,0.f,0.f); acc[r][1] = acc[r][0]; }

#define FMA4(A, S, Bv) { A.x += (S)*(Bv).x; A.y += (S)*(Bv).y; A.z += (S)*(Bv).z; A.w += (S)*(Bv).w; }
    for (int k0 = 0; k0 < 128; k0 += 32) {
        #pragma unroll
        for (int i = t; i < 1024; i += 256) {
            int m = i >> 3, c4 = i & 7;
            int node = m0 + m;
            float4 v = (node < NN) ? x4[(size_t)node * 32 + (k0 >> 2) + c4]
                                   : make_float4(0.f, 0.f, 0.f, 0.f);
            int kk = c4 * 4;
            xs[kk + 0][m] = v.x; xs[kk + 1][m] = v.y;
            xs[kk + 2][m] = v.z; xs[kk + 3][m] = v.w;
        }
        #pragma unroll
        for (int i = t; i < 1024; i += 256) {
            int kk = i >> 5, c4 = i & 31;
            *(float4*)&ws[kk][c4 * 4] = *(const float4*)&g_Wall[(size_t)(k0 + kk) * 512 + col0 + c4 * 4];
        }
        __syncthreads();

        #pragma unroll
        for (int kk = 0; kk < 32; kk++) {
            float4 a0 = *(const float4*)&xs[kk][tm * 8];
            float4 a1 = *(const float4*)&xs[kk][tm * 8 + 4];
            float4 b0 = *(const float4*)&ws[kk][tn * 8];
            float4 b1 = *(const float4*)&ws[kk][tn * 8 + 4];
            FMA4(acc[0][0], a0.x, b0); FMA4(acc[0][1], a0.x, b1);
            FMA4(acc[1][0], a0.y, b0); FMA4(acc[1][1], a0.y, b1);
            FMA4(acc[2][0], a0.z, b0); FMA4(acc[2][1], a0.z, b1);
            FMA4(acc[3][0], a0.w, b0); FMA4(acc[3][1], a0.w, b1);
            FMA4(acc[4][0], a1.x, b0); FMA4(acc[4][1], a1.x, b1);
            FMA4(acc[5][0], a1.y, b0); FMA4(acc[5][1], a1.y, b1);
            FMA4(acc[6][0], a1.z, b0); FMA4(acc[6][1], a1.z, b1);
            FMA4(acc[7][0], a1.w, b0); FMA4(acc[7][1], a1.w, b1);
        }
        __syncthreads();
    }

    float4 bb0 = *(const float4*)&g_ball[col0 + tn * 8];
    float4 bb1 = *(const float4*)&g_ball[col0 + tn * 8 + 4];
    #pragma unroll
    for (int r = 0; r < 8; r++) {
        int node = m0 + tm * 8 + r;
        if (node >= NN) break;
        float4 o0 = acc[r][0]; o0.x += bb0.x; o0.y += bb0.y; o0.z += bb0.z; o0.w += bb0.w;
        float4 o1 = acc[r][1]; o1.x += bb1.x; o1.y += bb1.y; o1.z += bb1.z; o1.w += bb1.w;
        float* p = dptr + (size_t)node * 128 + tn * 8;
        *(float4*)p = o0;
        *(float4*)(p + 4) = o1;
    }
}

// ---------------------------------------------------------------------------
// K1b: z GEMM from q: z[n,h,d] = sum_c q[n,h,c] * WeT[h][c][d], k=64.
// launch_bounds (256,3) to lift occupancy (was regs=95 -> occ 24%).
// ---------------------------------------------------------------------------
__global__ void __launch_bounds__(256, 3)
k_gemmz()
{
    __shared__ float xs[32][132];   // [k][m] transposed q_h panel
    __shared__ float ws[32][68];    // [k][n]
    const int t = threadIdx.x;
    const int head = blockIdx.y / 3;
    const int nt = blockIdx.y % 3;
    const int col0 = nt * 64;
    const int m0 = blockIdx.x * 128;

    const float4* q4 = (const float4*)g_q;
    const float4* wt4 = (const float4*)(g_WeT + head * 12288);
    const int tn = t & 15, tm = t >> 4;

    float4 acc[8];
    #pragma unroll
    for (int r = 0; r < 8; r++) acc[r] = make_float4(0.f, 0.f, 0.f, 0.f);

    for (int k0 = 0; k0 < 64; k0 += 32) {
        #pragma unroll
        for (int i = t; i < 1024; i += 256) {
            int m = i >> 3, c4 = i & 7;
            int node = m0 + m;
            float4 v = (node < NN) ? q4[(size_t)node * 32 + head * 16 + (k0 >> 2) + c4]
                                   : make_float4(0.f, 0.f, 0.f, 0.f);
            int kk = c4 * 4;
            xs[kk + 0][m] = v.x; xs[kk + 1][m] = v.y;
            xs[kk + 2][m] = v.z; xs[kk + 3][m] = v.w;
        }
        #pragma unroll
        for (int i = t; i < 512; i += 256) {
            int kk = i >> 4, c4 = i & 15;
            *(float4*)&ws[kk][c4 * 4] = wt4[(size_t)(k0 + kk) * 48 + nt * 16 + c4];
        }
        __syncthreads();

        #pragma unroll
        for (int kk = 0; kk < 32; kk++) {
            float4 a0 = *(const float4*)&xs[kk][tm * 8];
            float4 a1 = *(const float4*)&xs[kk][tm * 8 + 4];
            float4 b0 = *(const float4*)&ws[kk][tn * 4];
            FMA4(acc[0], a0.x, b0);
            FMA4(acc[1], a0.y, b0);
            FMA4(acc[2], a0.z, b0);
            FMA4(acc[3], a0.w, b0);
            FMA4(acc[4], a1.x, b0);
            FMA4(acc[5], a1.y, b0);
            FMA4(acc[6], a1.z, b0);
            FMA4(acc[7], a1.w, b0);
        }
        __syncthreads();
    }
#undef FMA4

    float* zf = (float*)g_z;
    #pragma unroll
    for (int r = 0; r < 8; r++) {
        int node = m0 + tm * 8 + r;
        if (node >= NN) break;
        *(float4*)&zf[(size_t)node * 384 + head * 192 + col0 + tn * 4] = acc[r];
    }
}

// ---------------------------------------------------------------------------
// Counting sort by dst
// ---------------------------------------------------------------------------
__global__ void k_hist(const void* __restrict__ ei) {
    const int e = blockIdx.x * 256 + threadIdx.x;
    if (e >= EE) return;
    int dst = g_is64 ? (int)((const long long*)ei)[EE + e] : ((const int*)ei)[EE + e];
    atomicAdd(&g_cnt[dst], 1);
}

__global__ void k_scanA() {
    __shared__ int s[512];
    const int tid = threadIdx.x;
    const int i = blockIdx.x * 512 + tid;
    int c = (i < NN) ? g_cnt[i] : 0;
    s[tid] = c;
    __syncthreads();
    #pragma unroll
    for (int o = 1; o < 512; o <<= 1) {
        int v = (tid >= o) ? s[tid - o] : 0;
        __syncthreads();
        if (tid >= o) s[tid] += v;
        __syncthreads();
    }
    if (i < NN) g_offA[i] = s[tid] - c;
    if (tid == 511) g_bsum[blockIdx.x] = s[511];
}

__global__ void k_scanB(int nchunks) {
    if (threadIdx.x == 0) {
        int run = 0;
        for (int b = 0; b < nchunks; b++) { g_bpre[b] = run; run += g_bsum[b]; }
        g_off[NN] = EE;
    }
}

__global__ void k_scanC() {
    const int i = blockIdx.x * 512 + threadIdx.x;
    if (i < NN) {
        int v = g_offA[i] + g_bpre[blockIdx.x];
        g_off[i] = v;
        g_pos[i] = v;
    }
}

__global__ void k_scatter(const void* __restrict__ ei) {
    const int e = blockIdx.x * 256 + threadIdx.x;
    if (e >= EE) return;
    int dst = g_is64 ? (int)((const long long*)ei)[EE + e] : ((const int*)ei)[EE + e];
    int p = atomicAdd(&g_pos[dst], 1);
    g_eid[p] = e;
}

// ---------------------------------------------------------------------------
// K2: warp per dst segment, lane-batched edge prefetch (MLP=32), register
// accumulation, single write.  (R10 version — best measured end-to-end)
// ---------------------------------------------------------------------------
__global__ void __launch_bounds__(256)
k_edge2(const void* __restrict__ ei,
        const float* __restrict__ tt,
        const float* __restrict__ lu,
        const float4* __restrict__ msg4,
        const float* __restrict__ tw,
        const float* __restrict__ tb)
{
    const int w = threadIdx.x >> 5, lane = threadIdx.x & 31;
    const int dst = blockIdx.x * 8 + w;
    if (dst >= NN) return;
    const int is64 = g_is64;
    const int beg = g_off[dst], end = g_off[dst + 1];

    const int lq = lane & 15;
    const float4 tw4 = ((const float4*)tw)[lq];
    const float4 tb4 = ((const float4*)tb)[lq];
    const float4 q4 = g_q[(size_t)dst * 32 + lane];
    const size_t zb0 = (size_t)dst * 96;
    const float4 za = g_z[zb0 + lane];
    const float4 zb = g_z[zb0 + 32 + lane];
    const float4 zc = g_z[zb0 + 64 + lane];

    float4 aT = make_float4(0.f, 0.f, 0.f, 0.f), aV = aT, aM0 = aT, aM1 = aT;
    float s0 = 0.f, s1 = 0.f;

    for (int base = beg; base < end; base += 32) {
        const int cnt = min(32, end - base);
        int eidl = 0, srcl = 0; float rell = 0.f;
        if (lane < cnt) {
            eidl = g_eid[base + lane];
            long long s = is64 ? ((const long long*)ei)[eidl]
                               : (long long)((const int*)ei)[eidl];
            srcl = (int)s;
            rell = tt[eidl] - lu[s];
        }

        for (int j = 0; j < cnt; j++) {
            const int eid = __shfl_sync(0xffffffffu, eidl, j);
            const int src = __shfl_sync(0xffffffffu, srcl, j);
            const float rel = __shfl_sync(0xffffffffu, rell, j);

            const size_t mb = (size_t)eid * 32;
            float4 k4 = g_k[(size_t)src * 32 + lane];
            float4 v4 = g_v[(size_t)src * 32 + lane];
            float4 m4 = msg4[mb + lane];

            float4 ev;
            ev.x = __cosf(rel * tw4.x + tb4.x);
            ev.y = __cosf(rel * tw4.y + tb4.y);
            ev.z = __cosf(rel * tw4.z + tb4.z);
            ev.w = __cosf(rel * tw4.w + tb4.w);

            float qk = dot4(q4, k4);
            float4 Aa = (lane < 16) ? ev : msg4[mb + lane - 16];
            float4 Ab = (lane < 16) ? msg4[mb + lane + 16] : ev;
            float pb = dot4(zb, Ab) + qk;
            float p0 = dot4(za, Aa) + ((lane < 16) ? pb : 0.f);
            float p1 = dot4(zc, m4) + ((lane < 16) ? 0.f : pb);
            #pragma unroll
            for (int o = 16; o >= 1; o >>= 1) {
                p0 += __shfl_xor_sync(0xffffffffu, p0, o);
                p1 += __shfl_xor_sync(0xffffffffu, p1, o);
            }

            float w0 = __expf(0.125f * p0);
            float w1 = __expf(0.125f * p1);

            float sc = (lane < 16) ? w0 : w1;
            aT.x += sc * ev.x; aT.y += sc * ev.y; aT.z += sc * ev.z; aT.w += sc * ev.w;
            aV.x += sc * v4.x; aV.y += sc * v4.y; aV.z += sc * v4.z; aV.w += sc * v4.w;
            aM0.x += w0 * m4.x; aM0.y += w0 * m4.y; aM0.z += w0 * m4.z; aM0.w += w0 * m4.w;
            aM1.x += w1 * m4.x; aM1.y += w1 * m4.y; aM1.z += w1 * m4.z; aM1.w += w1 * m4.w;
            s0 += w0; s1 += w1;
        }
    }

    g_aggT[(size_t)dst * 32 + lane] = aT;
    g_aggV[(size_t)dst * 32 + lane] = aV;
    g_aggM[(size_t)dst * 64 + lane]      = aM0;
    g_aggM[(size_t)dst * 64 + 32 + lane] = aM1;
    if (lane == 0) g_asum[dst] = make_float2(s0, s1);
}

// ---------------------------------------------------------------------------
// K3: out[n,h,c] += (aggV + sum_d aggE[n,h,d]*We[d,j]) / asum[n,h]
// We transposed in smem (stride 204: 16B-aligned, phase-conflict-free .128),
// vectorized dot4 over d-quads (5 LDS.128 per 16 FFMA vs 5 LDS per 4 FFMA).
// ---------------------------------------------------------------------------
__global__ void k_final(const float* __restrict__ We, float* __restrict__ out)
{
    extern __shared__ float smf[];
    float* WeT = smf;                 // [128][204]  WeT[j*204+d] = We[d*128+j]
    float* sA  = smf + 128 * 204;     // [4 nodes][400]: h*192 + d
    float* sS  = sA + 4 * 400;        // 8 asums
    const int t = threadIdx.x;        // 128
    const int j = t, h = t >> 6;

    for (int d = 0; d < 192; d++)
        WeT[j * 204 + d] = We[d * 128 + j];

    const float4* w4 = (const float4*)(WeT + j * 204);

    for (int q0 = blockIdx.x * 4; q0 < NN; q0 += gridDim.x * 4) {
        __syncthreads();
        for (int i = t; i < 384; i += 128) {
            int ni = i / 96, m = i % 96;
            int node = q0 + ni;
            int hh = m / 48, d4 = m % 48;
            float4 val = (d4 < 16) ? g_aggT[(size_t)node * 32 + hh * 16 + d4]
                                   : g_aggM[(size_t)node * 64 + hh * 32 + (d4 - 16)];
            *(float4*)&sA[ni * 400 + hh * 192 + d4 * 4] = val;
        }
        if (t < 8) sS[t] = ((const float*)g_asum)[(size_t)(q0 + (t >> 1)) * 2 + (t & 1)];
        __syncthreads();

        const float4* a0 = (const float4*)(sA + 0 * 400 + h * 192);
        const float4* a1 = (const float4*)(sA + 1 * 400 + h * 192);
        const float4* a2 = (const float4*)(sA + 2 * 400 + h * 192);
        const float4* a3 = (const float4*)(sA + 3 * 400 + h * 192);
        float acc0 = 0.f, acc1 = 0.f, acc2 = 0.f, acc3 = 0.f;
        #pragma unroll 4
        for (int dq = 0; dq < 48; dq++) {
            float4 wv = w4[dq];
            acc0 += dot4(wv, a0[dq]);
            acc1 += dot4(wv, a1[dq]);
            acc2 += dot4(wv, a2[dq]);
            acc3 += dot4(wv, a3[dq]);
        }

        const float* gv = (const float*)g_aggV;
        size_t n0 = (size_t)q0;
        out[(n0 + 0) * 128 + j] += (gv[(n0 + 0) * 128 + j] + acc0) * (1.f / (sS[0 + h] + 1e-16f));
        out[(n0 + 1) * 128 + j] += (gv[(n0 + 1) * 128 + j] + acc1) * (1.f / (sS[2 + h] + 1e-16f));
        out[(n0 + 2) * 128 + j] += (gv[(n0 + 2) * 128 + j] + acc2) * (1.f / (sS[4 + h] + 1e-16f));
        out[(n0 + 3) * 128 + j] += (gv[(n0 + 3) * 128 + j] + acc3) * (1.f / (sS[6 + h] + 1e-16f));
    }
}

// ---------------------------------------------------------------------------
extern "C" void kernel_launch(void* const* d_in, const int* in_sizes, int n_in,
                              void* d_out, int out_size)
{
    const float* x  = (const float*)d_in[0];
    const float* lu = (const float*)d_in[1];
    const float* tt = (const float*)d_in[2];
    const float* msg = (const float*)d_in[3];
    const float* tw = (const float*)d_in[4];
    const float* tb = (const float*)d_in[5];
    const float* Wq = (const float*)d_in[6];
    const float* bq = (const float*)d_in[7];
    const float* Wk = (const float*)d_in[8];
    const float* bk = (const float*)d_in[9];
    const float* Wv = (const float*)d_in[10];
    const float* bv = (const float*)d_in[11];
    const float* We = (const float*)d_in[12];
    const float* Ws = (const float*)d_in[13];
    const float* bs = (const float*)d_in[14];
    const void* ei  = d_in[15];
    float* out = (float*)d_out;

    const int FINAL_SMEM = (128 * 204 + 4 * 400 + 8) * 4;   // 110880
    cudaFuncSetAttribute(k_final, cudaFuncAttributeMaxDynamicSharedMemorySize, FINAL_SMEM);

    void* pcnt;
    cudaGetSymbolAddress(&pcnt, g_cnt);
    cudaMemsetAsync(pcnt, 0, NN * sizeof(int));

    const int NCHUNK = (NN + 511) / 512;   // 98

    k_detect<<<1, 1>>>((const int*)ei);
    k_prep<<<353, 256>>>(Wq, bq, Wk, bk, Wv, bv, Ws, bs, We);
    k_gemm<<<dim3(391, 4, 1), 256>>>(x, out);
    k_gemmz<<<dim3(391, 6, 1), 256>>>();
    k_hist<<<(EE + 255) / 256, 256>>>(ei);
    k_scanA<<<NCHUNK, 512>>>();
    k_scanB<<<1, 32>>>(NCHUNK);
    k_scanC<<<NCHUNK, 512>>>();
    k_scatter<<<(EE + 255) / 256, 256>>>(ei);
    k_edge2<<<(NN + 7) / 8, 256>>>(ei, tt, lu, (const float4*)msg, tw, tb);
    k_final<<<592, 128, FINAL_SMEM>>>(We, out);
}

// round 16
// speedup vs baseline: 1.2996x; 1.0538x over previous
#include <cuda_runtime.h>
#include <math.h>

#define NN 50000
#define EE 500000

typedef unsigned long long u64;

// node-space tables
__device__ __align__(16) float4 g_q[NN * 32];
__device__ __align__(16) float4 g_k[NN * 32];
__device__ __align__(16) float4 g_v[NN * 32];
__device__ __align__(16) float4 g_z[NN * 96];      // [n][2][192] flat [n][384]
// per-dst aggregates (written once by k_edge2; no memsets needed)
__device__ __align__(16) float4 g_aggT[NN * 32];   // [n][2][64]   sum w*enc
__device__ __align__(16) float4 g_aggM[NN * 64];   // [n][2][128]  sum w*msg
__device__ __align__(16) float4 g_aggV[NN * 32];   // [n][2][64]   sum w*v[src]
__device__ __align__(8)  float2 g_asum[NN];        // [n][2]       sum w
__device__ int g_is64;
// combined weights: cols [q(0) k(128) v(256) skip(384)]
__device__ __align__(16) float g_Wall[128 * 512];
__device__ __align__(16) float g_ball[512];
// transposed We per head: g_WeT[h][c][d] = We[d*128 + h*64 + c]
__device__ __align__(16) float g_WeT[2 * 64 * 192];
// counting-sort scratch
__device__ int g_cnt[NN];
__device__ int g_offA[NN];
__device__ int g_bsum[128];
__device__ int g_bpre[128];
__device__ int g_off[NN + 1];
__device__ int g_pos[NN];
__device__ int g_eid[EE];

static __device__ __forceinline__ float dot4(float4 a, float4 b) {
    return a.x * b.x + a.y * b.y + a.z * b.z + a.w * b.w;
}
// packed fp32 helpers (FFMA2 path — 2 fp32 MACs per issue slot)
static __device__ __forceinline__ u64 pack2(float x) {
    u64 r; asm("mov.b64 %0, {%1, %1};" : "=l"(r) : "f"(x)); return r;
}
static __device__ __forceinline__ void fma2(u64& d, u64 a, u64 b) {
    asm("fma.rn.f32x2 %0, %1, %2, %0;" : "+l"(d) : "l"(a), "l"(b));
}
static __device__ __forceinline__ float2 unpack2(u64 v) {
    float lo, hi; asm("mov.b64 {%0, %1}, %2;" : "=f"(lo), "=f"(hi) : "l"(v));
    return make_float2(lo, hi);
}

// ---------------------------------------------------------------------------
__global__ void k_detect(const int* __restrict__ ei32) {
    int odd_or = 0;
    #pragma unroll
    for (int i = 1; i < 64; i += 2) odd_or |= ei32[i];
    g_is64 = (odd_or == 0) ? 1 : 0;
}

// ---------------------------------------------------------------------------
// Kp: Wall [128][512] copy + bias [512] + transposed We table.
// ---------------------------------------------------------------------------
__global__ void k_prep(const float* __restrict__ Wq, const float* __restrict__ bq,
                       const float* __restrict__ Wk, const float* __restrict__ bk,
                       const float* __restrict__ Wv, const float* __restrict__ bv,
                       const float* __restrict__ Ws, const float* __restrict__ bs,
                       const float* __restrict__ We)
{
    int u = blockIdx.x * 256 + threadIdx.x;
    if (u < 128 * 512) {
        int j = u >> 9, c = u & 511;
        const float* src = (c < 128) ? Wq : (c < 256) ? Wk : (c < 384) ? Wv : Ws;
        g_Wall[u] = src[j * 128 + (c & 127)];
    } else if (u < 128 * 512 + 2 * 64 * 192) {
        int v = u - 128 * 512;
        int h = v / 12288, r = v % 12288;
        int c = r / 192, d = r % 192;
        g_WeT[v] = We[d * 128 + h * 64 + c];
    } else if (u < 128 * 512 + 2 * 64 * 192 + 512) {
        int c = u - (128 * 512 + 2 * 64 * 192);
        const float* src = (c < 128) ? bq : (c < 256) ? bk : (c < 384) ? bv : bs;
        g_ball[c] = src[c & 127];
    }
}

// ---------------------------------------------------------------------------
// K1: node GEMM [50000,128] @ [128,512] (q,k,v,skip). Tile 128x128, 8x8/thr.
// Mainloop in packed f32x2 (FFMA2): 32 fma2 + 8 packs per k-step vs 64 FFMA.
// Bit-identical to the scalar version.
// ---------------------------------------------------------------------------
__global__ void __launch_bounds__(256, 2)
k_gemm(const float* __restrict__ x, float* __restrict__ out)
{
    __shared__ float xs[32][132];   // [k][m] transposed x panel
    __shared__ float ws[32][128];   // [k][n]
    const int t = threadIdx.x;
    const int y = blockIdx.y;
    const int col0 = y * 128;

    float* dptr;
    if      (y == 0) dptr = (float*)g_q;
    else if (y == 1) dptr = (float*)g_k;
    else if (y == 2) dptr = (float*)g_v;
    else             dptr = out;

    const int m0 = blockIdx.x * 128;
    const float4* x4 = (const float4*)x;
    const int tn = t & 15, tm = t >> 4;

    u64 acc[8][4];
    #pragma unroll
    for (int r = 0; r < 8; r++)
        #pragma unroll
        for (int i = 0; i < 4; i++) acc[r][i] = 0ull;

    for (int k0 = 0; k0 < 128; k0 += 32) {
        #pragma unroll
        for (int i = t; i < 1024; i += 256) {
            int m = i >> 3, c4 = i & 7;
            int node = m0 + m;
            float4 v = (node < NN) ? x4[(size_t)node * 32 + (k0 >> 2) + c4]
                                   : make_float4(0.f, 0.f, 0.f, 0.f);
            int kk = c4 * 4;
            xs[kk + 0][m] = v.x; xs[kk + 1][m] = v.y;
            xs[kk + 2][m] = v.z; xs[kk + 3][m] = v.w;
        }
        #pragma unroll
        for (int i = t; i < 1024; i += 256) {
            int kk = i >> 5, c4 = i & 31;
            *(float4*)&ws[kk][c4 * 4] = *(const float4*)&g_Wall[(size_t)(k0 + kk) * 512 + col0 + c4 * 4];
        }
        __syncthreads();

        #pragma unroll
        for (int kk = 0; kk < 32; kk++) {
            float4 a0 = *(const float4*)&xs[kk][tm * 8];
            float4 a1 = *(const float4*)&xs[kk][tm * 8 + 4];
            ulonglong2 b0 = *(const ulonglong2*)&ws[kk][tn * 8];
            ulonglong2 b1 = *(const ulonglong2*)&ws[kk][tn * 8 + 4];
            u64 s;
            s = pack2(a0.x); fma2(acc[0][0], s, b0.x); fma2(acc[0][1], s, b0.y); fma2(acc[0][2], s, b1.x); fma2(acc[0][3], s, b1.y);
            s = pack2(a0.y); fma2(acc[1][0], s, b0.x); fma2(acc[1][1], s, b0.y); fma2(acc[1][2], s, b1.x); fma2(acc[1][3], s, b1.y);
            s = pack2(a0.z); fma2(acc[2][0], s, b0.x); fma2(acc[2][1], s, b0.y); fma2(acc[2][2], s, b1.x); fma2(acc[2][3], s, b1.y);
            s = pack2(a0.w); fma2(acc[3][0], s, b0.x); fma2(acc[3][1], s, b0.y); fma2(acc[3][2], s, b1.x); fma2(acc[3][3], s, b1.y);
            s = pack2(a1.x); fma2(acc[4][0], s, b0.x); fma2(acc[4][1], s, b0.y); fma2(acc[4][2], s, b1.x); fma2(acc[4][3], s, b1.y);
            s = pack2(a1.y); fma2(acc[5][0], s, b0.x); fma2(acc[5][1], s, b0.y); fma2(acc[5][2], s, b1.x); fma2(acc[5][3], s, b1.y);
            s = pack2(a1.z); fma2(acc[6][0], s, b0.x); fma2(acc[6][1], s, b0.y); fma2(acc[6][2], s, b1.x); fma2(acc[6][3], s, b1.y);
            s = pack2(a1.w); fma2(acc[7][0], s, b0.x); fma2(acc[7][1], s, b0.y); fma2(acc[7][2], s, b1.x); fma2(acc[7][3], s, b1.y);
        }
        __syncthreads();
    }

    float4 bb0 = *(const float4*)&g_ball[col0 + tn * 8];
    float4 bb1 = *(const float4*)&g_ball[col0 + tn * 8 + 4];
    #pragma unroll
    for (int r = 0; r < 8; r++) {
        int node = m0 + tm * 8 + r;
        if (node >= NN) break;
        float2 p0 = unpack2(acc[r][0]);
        float2 p1 = unpack2(acc[r][1]);
        float2 p2 = unpack2(acc[r][2]);
        float2 p3 = unpack2(acc[r][3]);
        float4 o0 = make_float4(p0.x + bb0.x, p0.y + bb0.y, p1.x + bb0.z, p1.y + bb0.w);
        float4 o1 = make_float4(p2.x + bb1.x, p2.y + bb1.y, p3.x + bb1.z, p3.y + bb1.w);
        float* p = dptr + (size_t)node * 128 + tn * 8;
        *(float4*)p = o0;
        *(float4*)(p + 4) = o1;
    }
}

// ---------------------------------------------------------------------------
// K1b: z GEMM from q: z[n,h,d] = sum_c q[n,h,c] * WeT[h][c][d], k=64.
// Packed f32x2 mainloop.
// ---------------------------------------------------------------------------
__global__ void __launch_bounds__(256, 3)
k_gemmz()
{
    __shared__ float xs[32][132];   // [k][m] transposed q_h panel
    __shared__ float ws[32][68];    // [k][n]
    const int t = threadIdx.x;
    const int head = blockIdx.y / 3;
    const int nt = blockIdx.y % 3;
    const int col0 = nt * 64;
    const int m0 = blockIdx.x * 128;

    const float4* q4 = (const float4*)g_q;
    const float4* wt4 = (const float4*)(g_WeT + head * 12288);
    const int tn = t & 15, tm = t >> 4;

    u64 acc[8][2];
    #pragma unroll
    for (int r = 0; r < 8; r++) { acc[r][0] = 0ull; acc[r][1] = 0ull; }

    for (int k0 = 0; k0 < 64; k0 += 32) {
        #pragma unroll
        for (int i = t; i < 1024; i += 256) {
            int m = i >> 3, c4 = i & 7;
            int node = m0 + m;
            float4 v = (node < NN) ? q4[(size_t)node * 32 + head * 16 + (k0 >> 2) + c4]
                                   : make_float4(0.f, 0.f, 0.f, 0.f);
            int kk = c4 * 4;
            xs[kk + 0][m] = v.x; xs[kk + 1][m] = v.y;
            xs[kk + 2][m] = v.z; xs[kk + 3][m] = v.w;
        }
        #pragma unroll
        for (int i = t; i < 512; i += 256) {
            int kk = i >> 4, c4 = i & 15;
            *(float4*)&ws[kk][c4 * 4] = wt4[(size_t)(k0 + kk) * 48 + nt * 16 + c4];
        }
        __syncthreads();

        #pragma unroll
        for (int kk = 0; kk < 32; kk++) {
            float4 a0 = *(const float4*)&xs[kk][tm * 8];
            float4 a1 = *(const float4*)&xs[kk][tm * 8 + 4];
            ulonglong2 b0 = *(const ulonglong2*)&ws[kk][tn * 4];
            u64 s;
            s = pack2(a0.x); fma2(acc[0][0], s, b0.x); fma2(acc[0][1], s, b0.y);
            s = pack2(a0.y); fma2(acc[1][0], s, b0.x); fma2(acc[1][1], s, b0.y);
            s = pack2(a0.z); fma2(acc[2][0], s, b0.x); fma2(acc[2][1], s, b0.y);
            s = pack2(a0.w); fma2(acc[3][0], s, b0.x); fma2(acc[3][1], s, b0.y);
            s = pack2(a1.x); fma2(acc[4][0], s, b0.x); fma2(acc[4][1], s, b0.y);
            s = pack2(a1.y); fma2(acc[5][0], s, b0.x); fma2(acc[5][1], s, b0.y);
            s = pack2(a1.z); fma2(acc[6][0], s, b0.x); fma2(acc[6][1], s, b0.y);
            s = pack2(a1.w); fma2(acc[7][0], s, b0.x); fma2(acc[7][1], s, b0.y);
        }
        __syncthreads();
    }

    float* zf = (float*)g_z;
    #pragma unroll
    for (int r = 0; r < 8; r++) {
        int node = m0 + tm * 8 + r;
        if (node >= NN) break;
        float2 p0 = unpack2(acc[r][0]);
        float2 p1 = unpack2(acc[r][1]);
        float4 o = make_float4(p0.x, p0.y, p1.x, p1.y);
        *(float4*)&zf[(size_t)node * 384 + head * 192 + col0 + tn * 4] = o;
    }
}

// ---------------------------------------------------------------------------
// Counting sort by dst
// ---------------------------------------------------------------------------
__global__ void k_hist(const void* __restrict__ ei) {
    const int e = blockIdx.x * 256 + threadIdx.x;
    if (e >= EE) return;
    int dst = g_is64 ? (int)((const long long*)ei)[EE + e] : ((const int*)ei)[EE + e];
    atomicAdd(&g_cnt[dst], 1);
}

__global__ void k_scanA() {
    __shared__ int s[512];
    const int tid = threadIdx.x;
    const int i = blockIdx.x * 512 + tid;
    int c = (i < NN) ? g_cnt[i] : 0;
    s[tid] = c;
    __syncthreads();
    #pragma unroll
    for (int o = 1; o < 512; o <<= 1) {
        int v = (tid >= o) ? s[tid - o] : 0;
        __syncthreads();
        if (tid >= o) s[tid] += v;
        __syncthreads();
    }
    if (i < NN) g_offA[i] = s[tid] - c;
    if (tid == 511) g_bsum[blockIdx.x] = s[511];
}

__global__ void k_scanB(int nchunks) {
    if (threadIdx.x == 0) {
        int run = 0;
        for (int b = 0; b < nchunks; b++) { g_bpre[b] = run; run += g_bsum[b]; }
        g_off[NN] = EE;
    }
}

__global__ void k_scanC() {
    const int i = blockIdx.x * 512 + threadIdx.x;
    if (i < NN) {
        int v = g_offA[i] + g_bpre[blockIdx.x];
        g_off[i] = v;
        g_pos[i] = v;
    }
}

__global__ void k_scatter(const void* __restrict__ ei) {
    const int e = blockIdx.x * 256 + threadIdx.x;
    if (e >= EE) return;
    int dst = g_is64 ? (int)((const long long*)ei)[EE + e] : ((const int*)ei)[EE + e];
    int p = atomicAdd(&g_pos[dst], 1);
    g_eid[p] = e;
}

// ---------------------------------------------------------------------------
// K2: warp per dst segment, lane-batched edge prefetch (MLP=32), register
// accumulation, single write.  (R10 version — best measured end-to-end)
// ---------------------------------------------------------------------------
__global__ void __launch_bounds__(256)
k_edge2(const void* __restrict__ ei,
        const float* __restrict__ tt,
        const float* __restrict__ lu,
        const float4* __restrict__ msg4,
        const float* __restrict__ tw,
        const float* __restrict__ tb)
{
    const int w = threadIdx.x >> 5, lane = threadIdx.x & 31;
    const int dst = blockIdx.x * 8 + w;
    if (dst >= NN) return;
    const int is64 = g_is64;
    const int beg = g_off[dst], end = g_off[dst + 1];

    const int lq = lane & 15;
    const float4 tw4 = ((const float4*)tw)[lq];
    const float4 tb4 = ((const float4*)tb)[lq];
    const float4 q4 = g_q[(size_t)dst * 32 + lane];
    const size_t zb0 = (size_t)dst * 96;
    const float4 za = g_z[zb0 + lane];
    const float4 zb = g_z[zb0 + 32 + lane];
    const float4 zc = g_z[zb0 + 64 + lane];

    float4 aT = make_float4(0.f, 0.f, 0.f, 0.f), aV = aT, aM0 = aT, aM1 = aT;
    float s0 = 0.f, s1 = 0.f;

    for (int base = beg; base < end; base += 32) {
        const int cnt = min(32, end - base);
        int eidl = 0, srcl = 0; float rell = 0.f;
        if (lane < cnt) {
            eidl = g_eid[base + lane];
            long long s = is64 ? ((const long long*)ei)[eidl]
                               : (long long)((const int*)ei)[eidl];
            srcl = (int)s;
            rell = tt[eidl] - lu[s];
        }

        for (int j = 0; j < cnt; j++) {
            const int eid = __shfl_sync(0xffffffffu, eidl, j);
            const int src = __shfl_sync(0xffffffffu, srcl, j);
            const float rel = __shfl_sync(0xffffffffu, rell, j);

            const size_t mb = (size_t)eid * 32;
            float4 k4 = g_k[(size_t)src * 32 + lane];
            float4 v4 = g_v[(size_t)src * 32 + lane];
            float4 m4 = msg4[mb + lane];

            float4 ev;
            ev.x = __cosf(rel * tw4.x + tb4.x);
            ev.y = __cosf(rel * tw4.y + tb4.y);
            ev.z = __cosf(rel * tw4.z + tb4.z);
            ev.w = __cosf(rel * tw4.w + tb4.w);

            float qk = dot4(q4, k4);
            float4 Aa = (lane < 16) ? ev : msg4[mb + lane - 16];
            float4 Ab = (lane < 16) ? msg4[mb + lane + 16] : ev;
            float pb = dot4(zb, Ab) + qk;
            float p0 = dot4(za, Aa) + ((lane < 16) ? pb : 0.f);
            float p1 = dot4(zc, m4) + ((lane < 16) ? 0.f : pb);
            #pragma unroll
            for (int o = 16; o >= 1; o >>= 1) {
                p0 += __shfl_xor_sync(0xffffffffu, p0, o);
                p1 += __shfl_xor_sync(0xffffffffu, p1, o);
            }

            float w0 = __expf(0.125f * p0);
            float w1 = __expf(0.125f * p1);

            float sc = (lane < 16) ? w0 : w1;
            aT.x += sc * ev.x; aT.y += sc * ev.y; aT.z += sc * ev.z; aT.w += sc * ev.w;
            aV.x += sc * v4.x; aV.y += sc * v4.y; aV.z += sc * v4.z; aV.w += sc * v4.w;
            aM0.x += w0 * m4.x; aM0.y += w0 * m4.y; aM0.z += w0 * m4.z; aM0.w += w0 * m4.w;
            aM1.x += w1 * m4.x; aM1.y += w1 * m4.y; aM1.z += w1 * m4.z; aM1.w += w1 * m4.w;
            s0 += w0; s1 += w1;
        }
    }

    g_aggT[(size_t)dst * 32 + lane] = aT;
    g_aggV[(size_t)dst * 32 + lane] = aV;
    g_aggM[(size_t)dst * 64 + lane]      = aM0;
    g_aggM[(size_t)dst * 64 + 32 + lane] = aM1;
    if (lane == 0) g_asum[dst] = make_float2(s0, s1);
}

// ---------------------------------------------------------------------------
// K3: out[n,h,c] += (aggV + sum_d aggE[n,h,d]*We[d,j]) / asum[n,h]
// Transposed-We smem layout, vectorized dot4.
// ---------------------------------------------------------------------------
__global__ void k_final(const float* __restrict__ We, float* __restrict__ out)
{
    extern __shared__ float smf[];
    float* WeT = smf;                 // [128][204]  WeT[j*204+d] = We[d*128+j]
    float* sA  = smf + 128 * 204;     // [4 nodes][400]: h*192 + d
    float* sS  = sA + 4 * 400;        // 8 asums
    const int t = threadIdx.x;        // 128
    const int j = t, h = t >> 6;

    for (int d = 0; d < 192; d++)
        WeT[j * 204 + d] = We[d * 128 + j];

    const float4* w4 = (const float4*)(WeT + j * 204);

    for (int q0 = blockIdx.x * 4; q0 < NN; q0 += gridDim.x * 4) {
        __syncthreads();
        for (int i = t; i < 384; i += 128) {
            int ni = i / 96, m = i % 96;
            int node = q0 + ni;
            int hh = m / 48, d4 = m % 48;
            float4 val = (d4 < 16) ? g_aggT[(size_t)node * 32 + hh * 16 + d4]
                                   : g_aggM[(size_t)node * 64 + hh * 32 + (d4 - 16)];
            *(float4*)&sA[ni * 400 + hh * 192 + d4 * 4] = val;
        }
        if (t < 8) sS[t] = ((const float*)g_asum)[(size_t)(q0 + (t >> 1)) * 2 + (t & 1)];
        __syncthreads();

        const float4* a0 = (const float4*)(sA + 0 * 400 + h * 192);
        const float4* a1 = (const float4*)(sA + 1 * 400 + h * 192);
        const float4* a2 = (const float4*)(sA + 2 * 400 + h * 192);
        const float4* a3 = (const float4*)(sA + 3 * 400 + h * 192);
        float acc0 = 0.f, acc1 = 0.f, acc2 = 0.f, acc3 = 0.f;
        #pragma unroll 4
        for (int dq = 0; dq < 48; dq++) {
            float4 wv = w4[dq];
            acc0 += dot4(wv, a0[dq]);
            acc1 += dot4(wv, a1[dq]);
            acc2 += dot4(wv, a2[dq]);
            acc3 += dot4(wv, a3[dq]);
        }

        const float* gv = (const float*)g_aggV;
        size_t n0 = (size_t)q0;
        out[(n0 + 0) * 128 + j] += (gv[(n0 + 0) * 128 + j] + acc0) * (1.f / (sS[0 + h] + 1e-16f));
        out[(n0 + 1) * 128 + j] += (gv[(n0 + 1) * 128 + j] + acc1) * (1.f / (sS[2 + h] + 1e-16f));
        out[(n0 + 2) * 128 + j] += (gv[(n0 + 2) * 128 + j] + acc2) * (1.f / (sS[4 + h] + 1e-16f));
        out[(n0 + 3) * 128 + j] += (gv[(n0 + 3) * 128 + j] + acc3) * (1.f / (sS[6 + h] + 1e-16f));
    }
}

// ---------------------------------------------------------------------------
extern "C" void kernel_launch(void* const* d_in, const int* in_sizes, int n_in,
                              void* d_out, int out_size)
{
    const float* x  = (const float*)d_in[0];
    const float* lu = (const float*)d_in[1];
    const float* tt = (const float*)d_in[2];
    const float* msg = (const float*)d_in[3];
    const float* tw = (const float*)d_in[4];
    const float* tb = (const float*)d_in[5];
    const float* Wq = (const float*)d_in[6];
    const float* bq = (const float*)d_in[7];
    const float* Wk = (const float*)d_in[8];
    const float* bk = (const float*)d_in[9];
    const float* Wv = (const float*)d_in[10];
    const float* bv = (const float*)d_in[11];
    const float* We = (const float*)d_in[12];
    const float* Ws = (const float*)d_in[13];
    const float* bs = (const float*)d_in[14];
    const void* ei  = d_in[15];
    float* out = (float*)d_out;

    const int FINAL_SMEM = (128 * 204 + 4 * 400 + 8) * 4;   // 110880
    cudaFuncSetAttribute(k_final, cudaFuncAttributeMaxDynamicSharedMemorySize, FINAL_SMEM);

    void* pcnt;
    cudaGetSymbolAddress(&pcnt, g_cnt);
    cudaMemsetAsync(pcnt, 0, NN * sizeof(int));

    const int NCHUNK = (NN + 511) / 512;   // 98

    k_detect<<<1, 1>>>((const int*)ei);
    k_prep<<<353, 256>>>(Wq, bq, Wk, bk, Wv, bv, Ws, bs, We);
    k_gemm<<<dim3(391, 4, 1), 256>>>(x, out);
    k_gemmz<<<dim3(391, 6, 1), 256>>>();
    k_hist<<<(EE + 255) / 256, 256>>>(ei);
    k_scanA<<<NCHUNK, 512>>>();
    k_scanB<<<1, 32>>>(NCHUNK);
    k_scanC<<<NCHUNK, 512>>>();
    k_scatter<<<(EE + 255) / 256, 256>>>(ei);
    k_edge2<<<(NN + 7) / 8, 256>>>(ei, tt, lu, (const float4*)msg, tw, tb);
    k_final<<<592, 128, FINAL_SMEM>>>(We, out);
}